// round 12
// baseline (speedup 1.0000x reference)
#include <cuda_runtime.h>
#include <cuda_fp16.h>
#include <cstdint>
#include <cstddef>

// ---------------------------------------------------------------------------
// Critic_Mix fused kernel (round 11): fp16 m16n8k16 mma.sync, BM=64, 256 thr,
// 2 CTAs/SM. R11: B operands loaded DIRECTLY from a fragment-ordered global
// weight image (2x LDG.128 per warp per j) — no weight SMEM buffer, no
// cp.async, no LDSM for B. Removes ~32% of per-stream l1tex traffic.
// Fragment mapping derived from the (verified) ldsm path; values identical.
// ---------------------------------------------------------------------------

#define THREADS   256
#define BM        64
#define BATCH     262144
#define NBLK      (BATCH / BM)

#define ACT_B      16384                 // 64 rows x 256B (128 fp16)
#define SMEM_BYTES (5 * ACT_B)           // 81920 -> 2 CTAs/SM easily

// Fragment-ordered weight image: per img 2048 uint4 (32KB):
//   index = wn*512 + j*64 + half*32 + t     (t = lane)
//   uint4 = regs r=0..3 for that lane: W[n][k pair] with
//   n = wn*32 + half*16 + (r>>1)*8 + t/4,  k = (2j+(r&1))*8 + (t%4)*2
__device__ uint4 g_wimg[30 * 2048];
__device__ float g_bimg[30 * 128];

struct Params {
    const float* x;
    const float* u;
    const float* mixf;
    const float* P;
    const float* W[2][3];
    const float* Bb[2][3];
    const float* W4[2];
    const float* b4[2];
    const float* tW[2][3];
    const float* tb[2][3];
    float*       out;
};

__device__ __forceinline__ uint32_t s2u(const void* p) {
    uint32_t a;
    asm("{ .reg .u64 t; cvta.to.shared.u64 t, %1; cvt.u32.u64 %0, t; }"
        : "=r"(a) : "l"(p));
    return a;
}
__device__ __forceinline__ void ldsm4(uint32_t* r, uint32_t addr) {
    asm volatile("ldmatrix.sync.aligned.m8n8.x4.shared.b16 {%0,%1,%2,%3}, [%4];"
                 : "=r"(r[0]), "=r"(r[1]), "=r"(r[2]), "=r"(r[3]) : "r"(addr));
}
__device__ __forceinline__ void mma16(float* c, const uint32_t* a,
                                      uint32_t b0, uint32_t b1) {
    asm volatile(
        "mma.sync.aligned.m16n8k16.row.col.f32.f16.f16.f32 "
        "{%0,%1,%2,%3}, {%4,%5,%6,%7}, {%8,%9}, {%0,%1,%2,%3};"
        : "+f"(c[0]), "+f"(c[1]), "+f"(c[2]), "+f"(c[3])
        : "r"(a[0]), "r"(a[1]), "r"(a[2]), "r"(a[3]), "r"(b0), "r"(b1));
}

// ---------------- preprocessing kernel ----------------
__global__ void prep_kernel(Params p) {
    const int idx = blockIdx.x * 256 + threadIdx.x;
    if (idx < 30 * 2048) {
        const int img  = idx >> 11;
        const int rem  = idx & 2047;
        const int wn   = rem >> 9;
        const int j    = (rem >> 6) & 7;
        const int half = (rem >> 5) & 1;
        const int t    = rem & 31;
        const int h = img / 15, rr = img % 15, L = rr / 5, s = rr % 5;
        const int O = (L == 2) ? 64 : 128;
        const float* W = (s == 4) ? p.W[h][L]
                                  : p.tW[h][L] + (size_t)s * O * 128;
        uint32_t w[4];
        #pragma unroll
        for (int r = 0; r < 4; r++) {
            const int n  = wn * 32 + half * 16 + (r >> 1) * 8 + (t >> 2);
            const int kk = (j * 2 + (r & 1)) * 8 + (t & 3) * 2;
            if (n < O) {
                __half2 hv = __floats2half2_rn(W[(size_t)n * 128 + kk],
                                               W[(size_t)n * 128 + kk + 1]);
                w[r] = *reinterpret_cast<uint32_t*>(&hv);
            } else {
                w[r] = 0u;
            }
        }
        g_wimg[img * 2048 + rem] = make_uint4(w[0], w[1], w[2], w[3]);
    } else if (idx < 30 * 2048 + 960) {
        const int b = idx - 30 * 2048;
        const int img = b >> 5, q = b & 31;
        const int h = img / 15, rr = img % 15, L = rr / 5, s = rr % 5;
        const int O = (L == 2) ? 64 : 128;
        const float* B = (s == 4) ? p.Bb[h][L] : p.tb[h][L] + s * O;
        const int o = q * 4;
        float4 v;
        v.x = (o + 0 < O) ? B[o + 0] : 0.f;
        v.y = (o + 1 < O) ? B[o + 1] : 0.f;
        v.z = (o + 2 < O) ? B[o + 2] : 0.f;
        v.w = (o + 3 < O) ? B[o + 3] : 0.f;
        *reinterpret_cast<float4*>(g_bimg + img * 128 + o) = v;
    }
}

// ---------------- main kernel ----------------
__global__ void __launch_bounds__(THREADS, 2)
critic_main(Params p) {
    extern __shared__ char smem[];
    const uint32_t sbase = s2u(smem);

    const int tid  = threadIdx.x;
    const int lane = tid & 31;
    const int wid  = tid >> 5;
    const int wm   = wid & 1;           // 2 warps over m
    const int wn   = wid >> 1;          // 4 warps over n
    const int mbase = wm * 32;
    const int nbase = wn * 32;
    const int lq = lane >> 2, lr = lane & 3;
    const int r8 = lane & 7, sel = lane >> 3;
    const int row0 = blockIdx.x * BM;
    const bool lowN = (wn < 2);

    const int rA0 = mbase + (sel & 1) * 8 + r8;
    const uint32_t eA4 = (uint32_t)(((sel >> 1) ^ r8) << 4);
    const uint32_t aoff0 = (uint32_t)rA0 * 256;
    const uint32_t aoff1 = aoff0 + 16 * 256;

    // epilogue store addressing (row&7 == lq)
    const uint32_t rbase = (uint32_t)(mbase + lq) * 256;
    uint32_t coff[4];
    #pragma unroll
    for (int nt = 0; nt < 4; nt++)
        coff[nt] = ((uint32_t)((((nbase >> 3) + nt) ^ lq) << 4)) + (uint32_t)lr * 4;

    const float m = __ldg(p.mixf);
    const float inv_m = 1.0f - m;
    float Pk[4];
    #pragma unroll
    for (int k = 0; k < 4; k++) Pk[k] = __ldg(p.P + k);

    for (int h = 0; h < 2; h++) {
        // ---- xu -> act buffer 4 (fp16, swizzled) ----
        {
            char* dst = smem + 4 * ACT_B;
            #pragma unroll
            for (int i = tid; i < BM * 16; i += THREADS) {
                const int r = i >> 4, ch = i & 15;
                float4 v0, v1;
                if (ch < 12) {
                    const float* src = p.x + (size_t)(row0 + r) * 96 + ch * 8;
                    v0 = *reinterpret_cast<const float4*>(src);
                    v1 = *reinterpret_cast<const float4*>(src + 4);
                } else {
                    const float* src = p.u + (size_t)(row0 + r) * 32 + (ch - 12) * 8;
                    v0 = *reinterpret_cast<const float4*>(src);
                    v1 = *reinterpret_cast<const float4*>(src + 4);
                }
                __half2 t0 = __floats2half2_rn(v0.x, v0.y);
                __half2 t1 = __floats2half2_rn(v0.z, v0.w);
                __half2 t2 = __floats2half2_rn(v1.x, v1.y);
                __half2 t3 = __floats2half2_rn(v1.z, v1.w);
                uint4 o;
                o.x = *reinterpret_cast<uint32_t*>(&t0);
                o.y = *reinterpret_cast<uint32_t*>(&t1);
                o.z = *reinterpret_cast<uint32_t*>(&t2);
                o.w = *reinterpret_cast<uint32_t*>(&t3);
                *reinterpret_cast<uint4*>(dst + r * 256 + ((ch ^ (r & 7)) << 4)) = o;
            }
        }

        float mix[2][4][4];
        for (int t = 0; t < 15; t++) {
            const int g = h * 15 + t;
            const int L = t / 5, s = t % 5;
            const bool is_main = (s == 4);
            const bool active  = (L < 2) || lowN;
            if (s == 0) {
                #pragma unroll
                for (int mt = 0; mt < 2; mt++)
                    #pragma unroll
                    for (int nt = 0; nt < 4; nt++)
                        #pragma unroll
                        for (int c = 0; c < 4; c++) mix[mt][nt][c] = 0.f;
            }

            __syncthreads();    // prev epilogue stores visible

            float acc[2][4][4];
            #pragma unroll
            for (int mt = 0; mt < 2; mt++)
                #pragma unroll
                for (int nt = 0; nt < 4; nt++)
                    #pragma unroll
                    for (int c = 0; c < 4; c++) acc[mt][nt][c] = 0.f;

            if (active) {
                const int inb = (L == 0) ? 4 : (is_main ? 4 : s);
                const uint32_t ab0 = sbase + (uint32_t)inb * ACT_B + aoff0;
                const uint32_t ab1 = sbase + (uint32_t)inb * ACT_B + aoff1;
                const uint4* bt = g_wimg + (size_t)g * 2048 + wn * 512 + lane;

                // depth-2 B prefetch pipeline (global -> regs)
                uint4 bq0[2], bq1[2];
                bq0[0] = __ldg(bt);       bq1[0] = __ldg(bt + 32);
                bq0[1] = __ldg(bt + 64);  bq1[1] = __ldg(bt + 96);

                #pragma unroll
                for (int j = 0; j < 8; j++) {
                    const int cur = j & 1;
                    uint32_t fa0[4], fa1[4];
                    const uint32_t tA = ((uint32_t)(j << 5)) ^ eA4;
                    ldsm4(fa0, ab0 + tA);
                    ldsm4(fa1, ab1 + tA);
                    uint4 p0, p1;
                    if (j < 6) {
                        p0 = __ldg(bt + (j + 2) * 64);
                        p1 = __ldg(bt + (j + 2) * 64 + 32);
                    }
                    const uint4 c0 = bq0[cur], c1 = bq1[cur];
                    mma16(acc[0][0], fa0, c0.x, c0.y);
                    mma16(acc[0][1], fa0, c0.z, c0.w);
                    mma16(acc[0][2], fa0, c1.x, c1.y);
                    mma16(acc[0][3], fa0, c1.z, c1.w);
                    mma16(acc[1][0], fa1, c0.x, c0.y);
                    mma16(acc[1][1], fa1, c0.z, c0.w);
                    mma16(acc[1][2], fa1, c1.x, c1.y);
                    mma16(acc[1][3], fa1, c1.z, c1.w);
                    if (j < 6) { bq0[cur] = p0; bq1[cur] = p1; }
                }
            }

            // bias via LDG (tiny, L2-hit); latency absorbed by the barrier
            float bias[4][2];
            {
                const float* bs = g_bimg + g * 128;
                #pragma unroll
                for (int nt = 0; nt < 4; nt++) {
                    bias[nt][0] = __ldg(bs + nbase + nt * 8 + lr * 2 + 0);
                    bias[nt][1] = __ldg(bs + nbase + nt * 8 + lr * 2 + 1);
                }
            }

            __syncthreads();    // act reads done -> epilogue may overwrite

            if (active) {
                const float sc = is_main ? inv_m : (m * Pk[s]);
                const bool do_store = is_main || (L < 2);
                char* outb = smem + (is_main ? 4 : s) * ACT_B;
                #pragma unroll
                for (int mt = 0; mt < 2; mt++)
                    #pragma unroll
                    for (int nt = 0; nt < 4; nt++)
                        #pragma unroll
                        for (int c2 = 0; c2 < 2; c2++) {
                            const float v0 = acc[mt][nt][c2 * 2 + 0] + bias[nt][0];
                            const float v1 = acc[mt][nt][c2 * 2 + 1] + bias[nt][1];
                            float o0, o1;
                            if (!is_main) {
                                mix[mt][nt][c2 * 2 + 0] = fmaf(sc, v0, mix[mt][nt][c2 * 2 + 0]);
                                mix[mt][nt][c2 * 2 + 1] = fmaf(sc, v1, mix[mt][nt][c2 * 2 + 1]);
                                o0 = v0; o1 = v1;
                            } else {
                                o0 = fmaf(sc, v0, mix[mt][nt][c2 * 2 + 0]);
                                o1 = fmaf(sc, v1, mix[mt][nt][c2 * 2 + 1]);
                            }
                            if (do_store) {
                                __half2 hv = __floats2half2_rn(fmaxf(o0, 0.f),
                                                               fmaxf(o1, 0.f));
                                *reinterpret_cast<uint32_t*>(
                                    smem + ((is_main ? 4 : s) * ACT_B) + rbase +
                                    mt * 4096 + c2 * 2048 + coff[nt])
                                    = *reinterpret_cast<uint32_t*>(&hv);
                            }
                            (void)outb;
                        }
            }
        }

        __syncthreads();
        // ---- final layer: out = h3 . W4 + b4 ----
        if (tid < BM) {
            float sum = __ldg(p.b4[h]);
            const float* W4 = p.W4[h];
            const char* hb = smem + 4 * ACT_B;
            #pragma unroll
            for (int k2 = 0; k2 < 64; k2++) {
                const __half hv = *reinterpret_cast<const __half*>(
                    hb + tid * 256 + (((k2 >> 3) ^ (tid & 7)) << 4) + (k2 & 7) * 2);
                sum = fmaf(__half2float(hv), __ldg(W4 + k2), sum);
            }
            p.out[(size_t)h * BATCH + row0 + tid] = sum;
        }
        __syncthreads();
    }
}

extern "C" void kernel_launch(void* const* d_in, const int* in_sizes, int n_in,
                              void* d_out, int out_size) {
    (void)in_sizes; (void)n_in; (void)out_size;
    Params p;
    p.x    = (const float*)d_in[0];
    p.u    = (const float*)d_in[1];
    p.mixf = (const float*)d_in[2];
    p.P    = (const float*)d_in[3];
    for (int h = 0; h < 2; h++) {
        const int base = 4 + h * 8;
        p.W[h][0]  = (const float*)d_in[base + 0];
        p.Bb[h][0] = (const float*)d_in[base + 1];
        p.W[h][1]  = (const float*)d_in[base + 2];
        p.Bb[h][1] = (const float*)d_in[base + 3];
        p.W[h][2]  = (const float*)d_in[base + 4];
        p.Bb[h][2] = (const float*)d_in[base + 5];
        p.W4[h]    = (const float*)d_in[base + 6];
        p.b4[h]    = (const float*)d_in[base + 7];
        const int tbase = 20 + h * 6;
        p.tW[h][0] = (const float*)d_in[tbase + 0];
        p.tb[h][0] = (const float*)d_in[tbase + 1];
        p.tW[h][1] = (const float*)d_in[tbase + 2];
        p.tb[h][1] = (const float*)d_in[tbase + 3];
        p.tW[h][2] = (const float*)d_in[tbase + 4];
        p.tb[h][2] = (const float*)d_in[tbase + 5];
    }
    p.out = (float*)d_out;

    prep_kernel<<<(30 * 2048 + 960 + 255) / 256, 256>>>(p);
    cudaFuncSetAttribute(critic_main,
                         cudaFuncAttributeMaxDynamicSharedMemorySize, SMEM_BYTES);
    critic_main<<<NBLK, THREADS, SMEM_BYTES>>>(p);
}